// round 8
// baseline (speedup 1.0000x reference)
#include <cuda_runtime.h>
#include <cuda_bf16.h>
#include <math.h>
#include <stdint.h>

// ---------------- problem constants ----------------
#define BATCH   2
#define SEQ     2048
#define T_TOK   4096
#define DMODEL  2048
#define NHEAD   16
#define QLORA   1536
#define KVLORA  512
#define DN      128
#define DR      64
#define DV      128
#define CDIM    576
#define QF_LD   (NHEAD*CDIM)   // 9216

typedef __nv_bfloat16 bf16;

// ---------------- scratch (static device memory) ----------------
__device__ float g_q_mixed [(size_t)T_TOK * QLORA];
__device__ float g_kv_mixed[(size_t)T_TOK * CDIM];
__device__ float g_q_rope  [(size_t)T_TOK * (NHEAD*DR)];
__device__ float g_scores  [(size_t)BATCH * NHEAD * SEQ * SEQ];

__device__ bf16 g_hidden_h [(size_t)T_TOK * DMODEL];
__device__ bf16 g_hidden_l [(size_t)T_TOK * DMODEL];
__device__ bf16 g_wqa_h    [(size_t)QLORA * DMODEL];
__device__ bf16 g_wqa_l    [(size_t)QLORA * DMODEL];
__device__ bf16 g_wkva_h   [(size_t)CDIM * DMODEL];
__device__ bf16 g_wkva_l   [(size_t)CDIM * DMODEL];
__device__ bf16 g_wqb_h    [(size_t)(NHEAD*DN) * QLORA];
__device__ bf16 g_wqb_l    [(size_t)(NHEAD*DN) * QLORA];
__device__ bf16 g_wqr_h    [(size_t)(NHEAD*DR) * QLORA];
__device__ bf16 g_wqr_l    [(size_t)(NHEAD*DR) * QLORA];
__device__ bf16 g_wo_h     [(size_t)DMODEL * (NHEAD*DV)];
__device__ bf16 g_wo_l     [(size_t)DMODEL * (NHEAD*DV)];
__device__ bf16 g_kupT_h   [(size_t)NHEAD * KVLORA * DN];
__device__ bf16 g_kupT_l   [(size_t)NHEAD * KVLORA * DN];
__device__ bf16 g_vup_h    [(size_t)NHEAD * DV * KVLORA];
__device__ bf16 g_vup_l    [(size_t)NHEAD * DV * KVLORA];
__device__ bf16 g_qlat_h   [(size_t)T_TOK * QLORA];
__device__ bf16 g_qlat_l   [(size_t)T_TOK * QLORA];
__device__ bf16 g_kfull_h  [(size_t)T_TOK * CDIM];
__device__ bf16 g_kfull_l  [(size_t)T_TOK * CDIM];
__device__ bf16 g_qnope_h  [(size_t)T_TOK * (NHEAD*DN)];
__device__ bf16 g_qnope_l  [(size_t)T_TOK * (NHEAD*DN)];
__device__ bf16 g_qfull_h  [(size_t)T_TOK * QF_LD];
__device__ bf16 g_qfull_l  [(size_t)T_TOK * QF_LD];
__device__ bf16 g_kvlatT_h [(size_t)BATCH * KVLORA * SEQ];
__device__ bf16 g_kvlatT_l [(size_t)BATCH * KVLORA * SEQ];
__device__ bf16 g_probs_h  [(size_t)BATCH * NHEAD * SEQ * SEQ];
__device__ bf16 g_probs_l  [(size_t)BATCH * NHEAD * SEQ * SEQ];
__device__ bf16 g_attn_h   [(size_t)BATCH * NHEAD * SEQ * KVLORA];
__device__ bf16 g_attn_l   [(size_t)BATCH * NHEAD * SEQ * KVLORA];
__device__ bf16 g_attnv_h  [(size_t)T_TOK * (NHEAD*DV)];
__device__ bf16 g_attnv_l  [(size_t)T_TOK * (NHEAD*DV)];
__device__ float g_cos[SEQ * 32];
__device__ float g_sin[SEQ * 32];

// ---------------- helpers ----------------
__device__ __forceinline__ uint32_t smem_u32(const void* p) {
    uint32_t a;
    asm("{ .reg .u64 t; cvta.to.shared.u64 t, %1; cvt.u32.u64 %0, t; }" : "=r"(a) : "l"(p));
    return a;
}
__device__ __forceinline__ void cpa16(uint32_t dst, const void* src, uint32_t sz) {
    asm volatile("cp.async.cg.shared.global [%0], [%1], 16, %2;"
                 :: "r"(dst), "l"(src), "r"(sz) : "memory");
}
__device__ __forceinline__ void ldm4(uint32_t* r, uint32_t a) {
    asm volatile("ldmatrix.sync.aligned.m8n8.x4.shared.b16 {%0,%1,%2,%3}, [%4];"
                 : "=r"(r[0]), "=r"(r[1]), "=r"(r[2]), "=r"(r[3]) : "r"(a));
}
__device__ __forceinline__ void mma16816(float* c, const uint32_t* a, const uint32_t* b) {
    asm volatile("mma.sync.aligned.m16n8k16.row.col.f32.bf16.bf16.f32 "
                 "{%0,%1,%2,%3}, {%4,%5,%6,%7}, {%8,%9}, {%0,%1,%2,%3};"
                 : "+f"(c[0]), "+f"(c[1]), "+f"(c[2]), "+f"(c[3])
                 : "r"(a[0]), "r"(a[1]), "r"(a[2]), "r"(a[3]), "r"(b[0]), "r"(b[1]));
}

// ---------------- HMMA batched split-bf16 NT GEMM ----------------
// C(MxN) = (Ah+Al)(MxK) * (Bh+Bl)(NxK)^T (drop lo*lo).  K%32==0, M%128==0.
// 128 threads, 4 warps, warp tile 64x64.  2-stage cp.async.
// smem per stage: A 128x(32hi|32lo) bf16 = 16KB, B same -> 32KB/stage.
#define GSMEM (2 * 32768 + 1024)

__global__ void __launch_bounds__(128, 2)
gemm_mma(const bf16* __restrict__ Ah, const bf16* __restrict__ Al,
         const bf16* __restrict__ Bh, const bf16* __restrict__ Bl,
         float* __restrict__ Cf, bf16* __restrict__ Chi, bf16* __restrict__ Clo,
         int N, int K, int lda, int ldb, int ldc,
         long long sAb, long long sAh_, long long sBb, long long sBh_,
         long long sCb, long long sCh_, int Hdim, int mode)
{
    extern __shared__ char smraw[];
    const uint32_t sbase = (smem_u32(smraw) + 1023) & ~1023u;

    const int tid  = threadIdx.x;
    const int lane = tid & 31;
    const int warp = tid >> 5;
    const int wm = (warp >> 1) * 64;     // 2 warps in M
    const int wn = (warp & 1) * 64;      // 2 warps in N

    const int z  = blockIdx.z;
    const int zb = z / Hdim, zh = z - zb * Hdim;
    const long long aoff = (long long)zb * sAb + (long long)zh * sAh_;
    const long long boff = (long long)zb * sBb + (long long)zh * sBh_;
    Ah += aoff; Al += aoff; Bh += boff; Bl += boff;

    const int m0 = blockIdx.y * 128;
    const int n0 = blockIdx.x * 128;
    const int KT = K >> 5;

    // ---- producer mapping: each thread owns one row of A and one row of B
    const int lr = tid;                      // row 0..127
    const bf16* pAh = Ah + (long long)(m0 + lr) * lda;
    const bf16* pAl = Al + (long long)(m0 + lr) * lda;
    const int brow = n0 + lr;
    const uint32_t bsz = (brow < N) ? 16u : 0u;
    const bf16* pBh = Bh + (long long)((brow < N) ? brow : 0) * ldb;
    const bf16* pBl = Bl + (long long)((brow < N) ? brow : 0) * ldb;
    uint32_t dOff[8];
    #pragma unroll
    for (int c = 0; c < 8; c++)
        dOff[c] = (uint32_t)(lr * 128 + ((c ^ (lr & 7)) << 4));

    // ---- consumer (ldmatrix) per-lane bases
    const int rowA = wm + (lane & 15);
    const uint32_t aA = (uint32_t)rowA * 128;
    const int e7A = rowA & 7;
    const int s4  = lane >> 4;
    const uint32_t aB = 16384u + (uint32_t)(wn + ((lane >> 4) << 3) + (lane & 7)) * 128;
    const int sB1 = (lane >> 3) & 1;
    const int e7B = lane & 7;

    float C[4][8][4];
    #pragma unroll
    for (int a = 0; a < 4; a++)
        #pragma unroll
        for (int b = 0; b < 8; b++)
            #pragma unroll
            for (int c = 0; c < 4; c++) C[a][b][c] = 0.f;

    // prologue: stage 0
    {
        const uint32_t sa = sbase;
        #pragma unroll
        for (int c2 = 0; c2 < 4; c2++) {
            cpa16(sa + dOff[c2],              pAh + c2 * 8, 16u);
            cpa16(sa + dOff[c2 + 4],          pAl + c2 * 8, 16u);
            cpa16(sa + 16384u + dOff[c2],     pBh + c2 * 8, bsz);
            cpa16(sa + 16384u + dOff[c2 + 4], pBl + c2 * 8, bsz);
        }
        asm volatile("cp.async.commit_group;" ::: "memory");
    }

    for (int t = 0; t < KT; t++) {
        const int s = t & 1;
        asm volatile("cp.async.wait_group 0;" ::: "memory");
        __syncthreads();
        if (t + 1 < KT) {
            const uint32_t sa = sbase + (uint32_t)(1 - s) * 32768u;
            const int kb = (t + 1) << 5;
            #pragma unroll
            for (int c2 = 0; c2 < 4; c2++) {
                cpa16(sa + dOff[c2],              pAh + kb + c2 * 8, 16u);
                cpa16(sa + dOff[c2 + 4],          pAl + kb + c2 * 8, 16u);
                cpa16(sa + 16384u + dOff[c2],     pBh + kb + c2 * 8, bsz);
                cpa16(sa + 16384u + dOff[c2 + 4], pBl + kb + c2 * 8, bsz);
            }
            asm volatile("cp.async.commit_group;" ::: "memory");
        }
        const uint32_t st = sbase + (uint32_t)s * 32768u;
        #pragma unroll
        for (int g = 0; g < 2; g++) {
            uint32_t Af[2][4][4];
            uint32_t Bfc[8][2];
            // A frags: hi + lo
            #pragma unroll
            for (int hl = 0; hl < 2; hl++) {
                const uint32_t posA = (uint32_t)((((hl << 2) | (g << 1) | s4) ^ e7A) << 4);
                #pragma unroll
                for (int mt = 0; mt < 4; mt++)
                    ldm4(Af[hl][mt], st + aA + mt * 2048u + posA);
            }
            // B hi frags
            {
                const uint32_t posB = (uint32_t)((((g << 1) | sB1) ^ e7B) << 4);
                #pragma unroll
                for (int ntp = 0; ntp < 4; ntp++) {
                    uint32_t r[4];
                    ldm4(r, st + aB + ntp * 2048u + posB);
                    Bfc[2 * ntp][0] = r[0]; Bfc[2 * ntp][1] = r[1];
                    Bfc[2 * ntp + 1][0] = r[2]; Bfc[2 * ntp + 1][1] = r[3];
                }
            }
            // pass 1: hi*hi
            #pragma unroll
            for (int mt = 0; mt < 4; mt++)
                #pragma unroll
                for (int nt = 0; nt < 8; nt++)
                    mma16816(C[mt][nt], Af[0][mt], Bfc[nt]);
            // pass 2: lo*hi
            #pragma unroll
            for (int mt = 0; mt < 4; mt++)
                #pragma unroll
                for (int nt = 0; nt < 8; nt++)
                    mma16816(C[mt][nt], Af[1][mt], Bfc[nt]);
            // B lo frags (overwrite)
            {
                const uint32_t posB = (uint32_t)((((1 << 2) | (g << 1) | sB1) ^ e7B) << 4);
                #pragma unroll
                for (int ntp = 0; ntp < 4; ntp++) {
                    uint32_t r[4];
                    ldm4(r, st + aB + ntp * 2048u + posB);
                    Bfc[2 * ntp][0] = r[0]; Bfc[2 * ntp][1] = r[1];
                    Bfc[2 * ntp + 1][0] = r[2]; Bfc[2 * ntp + 1][1] = r[3];
                }
            }
            // pass 3: hi*lo
            #pragma unroll
            for (int mt = 0; mt < 4; mt++)
                #pragma unroll
                for (int nt = 0; nt < 8; nt++)
                    mma16816(C[mt][nt], Af[0][mt], Bfc[nt]);
        }
        __syncthreads();
    }

    // ---- epilogue
    const long long cz = (long long)zb * sCb + (long long)zh * sCh_;
    #pragma unroll
    for (int mt = 0; mt < 4; mt++) {
        const int rbase = m0 + wm + mt * 16 + (lane >> 2);
        #pragma unroll
        for (int i = 0; i < 2; i++) {
            const long long ro = (long long)(rbase + 8 * i) * ldc + cz;
            #pragma unroll
            for (int nt = 0; nt < 8; nt++) {
                const int col = n0 + wn + nt * 8 + ((lane & 3) << 1);
                if (col < N) {
                    const float v0 = C[mt][nt][2 * i];
                    const float v1 = C[mt][nt][2 * i + 1];
                    if (mode == 0) {
                        *reinterpret_cast<float2*>(Cf + ro + col) = make_float2(v0, v1);
                    } else {
                        bf16 h0 = __float2bfloat16(v0);
                        bf16 h1 = __float2bfloat16(v1);
                        bf16 l0 = __float2bfloat16(v0 - __bfloat162float(h0));
                        bf16 l1 = __float2bfloat16(v1 - __bfloat162float(h1));
                        *reinterpret_cast<__nv_bfloat162*>(Chi + ro + col) =
                            __nv_bfloat162(h0, h1);
                        *reinterpret_cast<__nv_bfloat162*>(Clo + ro + col) =
                            __nv_bfloat162(l0, l1);
                    }
                }
            }
        }
    }
}

// ---------------- elementwise / reduction kernels ----------------
__device__ __forceinline__ void split_store(float v, bf16* hi, bf16* lo, size_t i) {
    bf16 h = __float2bfloat16(v);
    hi[i] = h;
    lo[i] = __float2bfloat16(v - __bfloat162float(h));
}
__device__ __forceinline__ __nv_bfloat162 hi2_of(float a, float b) {
    return __nv_bfloat162(__float2bfloat16(a), __float2bfloat16(b));
}
__device__ __forceinline__ __nv_bfloat162 lo2_of(float a, float b) {
    bf16 ha = __float2bfloat16(a), hb = __float2bfloat16(b);
    return __nv_bfloat162(__float2bfloat16(a - __bfloat162float(ha)),
                          __float2bfloat16(b - __bfloat162float(hb)));
}

// vectorized fp32 -> bf16 hi/lo pair (n % 4 == 0)
__global__ void cvt_pair_kernel(const float4* __restrict__ x,
                                __nv_bfloat162* __restrict__ hi2,
                                __nv_bfloat162* __restrict__ lo2, long long n4)
{
    long long i = (long long)blockIdx.x * 256 + threadIdx.x;
    if (i < n4) {
        float4 v = x[i];
        hi2[2 * i]     = hi2_of(v.x, v.y);
        hi2[2 * i + 1] = hi2_of(v.z, v.w);
        lo2[2 * i]     = lo2_of(v.x, v.y);
        lo2[2 * i + 1] = lo2_of(v.z, v.w);
    }
}

__device__ __forceinline__ float block_reduce(float v, float* red, bool is_max)
{
    #pragma unroll
    for (int o = 16; o > 0; o >>= 1) {
        float w = __shfl_xor_sync(0xffffffffu, v, o);
        v = is_max ? fmaxf(v, w) : (v + w);
    }
    if ((threadIdx.x & 31) == 0) red[threadIdx.x >> 5] = v;
    __syncthreads();
    float r = red[0];
    #pragma unroll
    for (int i = 1; i < 8; i++) r = is_max ? fmaxf(r, red[i]) : (r + red[i]);
    __syncthreads();
    return r;
}

__global__ __launch_bounds__(256) void ln_pair_kernel(
    const float* x, bf16* yhi, bf16* ylo,
    const float* __restrict__ g, const float* __restrict__ b,
    int L, int ldx, int ldy)
{
    __shared__ float s[QLORA];
    __shared__ float red[8];
    long long row = blockIdx.x;
    const float* xr = x + row * ldx;
    size_t ybase = (size_t)row * ldy;
    int tid = threadIdx.x;

    float part = 0.f;
    for (int i = tid; i < L; i += 256) { float v = xr[i]; s[i] = v; part += v; }
    float mu = block_reduce(part, red, false) / (float)L;
    float p2 = 0.f;
    for (int i = tid; i < L; i += 256) { float d = s[i] - mu; p2 += d * d; }
    float var  = block_reduce(p2, red, false) / (float)L;
    float rstd = rsqrtf(var + 1e-5f);
    for (int i = tid; i < L; i += 256)
        split_store((s[i] - mu) * rstd * g[i] + b[i], yhi, ylo, ybase + i);
}

// softmax over SEQ-wide rows: vectorized IO
__global__ __launch_bounds__(256) void softmax_pair_kernel(
    const float* __restrict__ sc, bf16* __restrict__ phi, bf16* __restrict__ plo, float scale)
{
    __shared__ float red[8];
    const float4* p4 = reinterpret_cast<const float4*>(sc + (long long)blockIdx.x * SEQ);
    size_t obase = (size_t)blockIdx.x * SEQ;
    int tid = threadIdx.x;
    float v[8];
    float4 a = p4[tid], b = p4[tid + 256];
    v[0]=a.x*scale; v[1]=a.y*scale; v[2]=a.z*scale; v[3]=a.w*scale;
    v[4]=b.x*scale; v[5]=b.y*scale; v[6]=b.z*scale; v[7]=b.w*scale;
    float mx = v[0];
    #pragma unroll
    for (int j = 1; j < 8; j++) mx = fmaxf(mx, v[j]);
    mx = block_reduce(mx, red, true);
    float sum = 0.f;
    #pragma unroll
    for (int j = 0; j < 8; j++) { v[j] = __expf(v[j] - mx); sum += v[j]; }
    sum = block_reduce(sum, red, false);
    float inv = 1.0f / sum;
    #pragma unroll
    for (int j = 0; j < 8; j++) v[j] *= inv;
    __nv_bfloat162* h2 = reinterpret_cast<__nv_bfloat162*>(phi + obase);
    __nv_bfloat162* l2 = reinterpret_cast<__nv_bfloat162*>(plo + obase);
    #pragma unroll
    for (int j = 0; j < 2; j++) {
        int f4 = tid + j * 256;
        h2[2 * f4]     = hi2_of(v[4*j],   v[4*j+1]);
        h2[2 * f4 + 1] = hi2_of(v[4*j+2], v[4*j+3]);
        l2[2 * f4]     = lo2_of(v[4*j],   v[4*j+1]);
        l2[2 * f4 + 1] = lo2_of(v[4*j+2], v[4*j+3]);
    }
}

__global__ void rope_tab_kernel(const int* __restrict__ pos)
{
    int idx = blockIdx.x * blockDim.x + threadIdx.x;
    if (idx >= SEQ * 32) return;
    int s = idx >> 5, i = idx & 31;
    double freq = exp(-((double)(2 * i) / 64.0) * log(10000.0));
    double ang  = (double)pos[s] * freq;
    g_cos[idx] = (float)cos(ang);
    g_sin[idx] = (float)sin(ang);
}

__global__ void rope_k_kernel()
{
    int idx = blockIdx.x * blockDim.x + threadIdx.x;
    if (idx >= T_TOK * 32) return;
    int t = idx >> 5, i = idx & 31;
    int s = t & (SEQ - 1);
    float c  = g_cos[(s << 5) + i];
    float sn = g_sin[(s << 5) + i];
    const float* x = g_kv_mixed + (size_t)t * CDIM + KVLORA;
    float x1 = x[i], x2 = x[i + 32];
    size_t o = (size_t)t * CDIM + KVLORA;
    split_store(x1 * c  - x2 * sn, g_kfull_h, g_kfull_l, o + i);
    split_store(x1 * sn + x2 * c,  g_kfull_h, g_kfull_l, o + i + 32);
}

__global__ void rope_q_kernel()
{
    int idx = blockIdx.x * blockDim.x + threadIdx.x;
    if (idx >= T_TOK * NHEAD * 32) return;
    int t = idx >> 9;
    int rem = idx & 511;
    int h = rem >> 5, i = rem & 31;
    int s = t & (SEQ - 1);
    float c  = g_cos[(s << 5) + i];
    float sn = g_sin[(s << 5) + i];
    const float* x = g_q_rope + (size_t)t * (NHEAD * DR) + h * DR;
    float x1 = x[i], x2 = x[i + 32];
    size_t o = (size_t)t * QF_LD + h * CDIM + KVLORA;
    split_store(x1 * c  - x2 * sn, g_qfull_h, g_qfull_l, o + i);
    split_store(x1 * sn + x2 * c,  g_qfull_h, g_qfull_l, o + i + 32);
}

__global__ void transpose_kup_kernel(const float* __restrict__ w_kvb)
{
    int idx = blockIdx.x * blockDim.x + threadIdx.x;
    if (idx >= NHEAD * KVLORA * DN) return;
    int h   = idx >> 16;
    int rem = idx & 65535;
    int r   = rem >> 7;
    int d   = rem & 127;
    split_store(w_kvb[(size_t)((h << 7) + d) * KVLORA + r], g_kupT_h, g_kupT_l, (size_t)idx);
}

__global__ void transpose_kv_kernel()
{
    int idx = blockIdx.x * blockDim.x + threadIdx.x;
    if (idx >= BATCH * KVLORA * SEQ) return;
    int b   = idx >> 20;
    int rem = idx & ((1 << 20) - 1);
    int r   = rem >> 11;
    int k   = rem & (SEQ - 1);
    size_t src = (size_t)((b << 11) + k) * CDIM + r;
    g_kvlatT_h[idx] = g_kfull_h[src];
    g_kvlatT_l[idx] = g_kfull_l[src];
}

// ---------------- host ----------------
extern "C" void kernel_launch(void* const* d_in, const int* in_sizes, int n_in,
                              void* d_out, int out_size)
{
    (void)in_sizes; (void)n_in; (void)out_size;
    const float* hidden   = (const float*)d_in[0];
    const float* w_qa     = (const float*)d_in[1];
    const float* ln_qa_g  = (const float*)d_in[2];
    const float* ln_qa_b  = (const float*)d_in[3];
    const float* w_qb     = (const float*)d_in[4];
    const float* w_qrope  = (const float*)d_in[5];
    const float* w_kva    = (const float*)d_in[6];
    const float* ln_kva_g = (const float*)d_in[7];
    const float* ln_kva_b = (const float*)d_in[8];
    const float* w_kvb    = (const float*)d_in[9];
    const float* w_o      = (const float*)d_in[10];
    const int*   pos      = (const int*)d_in[11];
    float* out = (float*)d_out;

    cudaFuncSetAttribute(gemm_mma, cudaFuncAttributeMaxDynamicSharedMemorySize, GSMEM);

    float *q_mixed, *kv_mixed, *q_rope, *scores;
    bf16 *hid_h,*hid_l,*wqa_h,*wqa_l,*wkva_h,*wkva_l,*wqb_h,*wqb_l,*wqr_h,*wqr_l,*wo_h,*wo_l;
    bf16 *kupT_h,*kupT_l,*vup_h,*vup_l,*qlat_h,*qlat_l,*kfull_h,*kfull_l,*qnope_h,*qnope_l;
    bf16 *qfull_h,*qfull_l,*kvlT_h,*kvlT_l,*pr_h,*pr_l,*at_h,*at_l,*av_h,*av_l;
    cudaGetSymbolAddress((void**)&q_mixed, g_q_mixed);
    cudaGetSymbolAddress((void**)&kv_mixed, g_kv_mixed);
    cudaGetSymbolAddress((void**)&q_rope, g_q_rope);
    cudaGetSymbolAddress((void**)&scores, g_scores);
    cudaGetSymbolAddress((void**)&hid_h, g_hidden_h);  cudaGetSymbolAddress((void**)&hid_l, g_hidden_l);
    cudaGetSymbolAddress((void**)&wqa_h, g_wqa_h);     cudaGetSymbolAddress((void**)&wqa_l, g_wqa_l);
    cudaGetSymbolAddress((void**)&wkva_h, g_wkva_h);   cudaGetSymbolAddress((void**)&wkva_l, g_wkva_l);
    cudaGetSymbolAddress((void**)&wqb_h, g_wqb_h);     cudaGetSymbolAddress((void**)&wqb_l, g_wqb_l);
    cudaGetSymbolAddress((void**)&wqr_h, g_wqr_h);     cudaGetSymbolAddress((void**)&wqr_l, g_wqr_l);
    cudaGetSymbolAddress((void**)&wo_h, g_wo_h);       cudaGetSymbolAddress((void**)&wo_l, g_wo_l);
    cudaGetSymbolAddress((void**)&kupT_h, g_kupT_h);   cudaGetSymbolAddress((void**)&kupT_l, g_kupT_l);
    cudaGetSymbolAddress((void**)&vup_h, g_vup_h);     cudaGetSymbolAddress((void**)&vup_l, g_vup_l);
    cudaGetSymbolAddress((void**)&qlat_h, g_qlat_h);   cudaGetSymbolAddress((void**)&qlat_l, g_qlat_l);
    cudaGetSymbolAddress((void**)&kfull_h, g_kfull_h); cudaGetSymbolAddress((void**)&kfull_l, g_kfull_l);
    cudaGetSymbolAddress((void**)&qnope_h, g_qnope_h); cudaGetSymbolAddress((void**)&qnope_l, g_qnope_l);
    cudaGetSymbolAddress((void**)&qfull_h, g_qfull_h); cudaGetSymbolAddress((void**)&qfull_l, g_qfull_l);
    cudaGetSymbolAddress((void**)&kvlT_h, g_kvlatT_h); cudaGetSymbolAddress((void**)&kvlT_l, g_kvlatT_l);
    cudaGetSymbolAddress((void**)&pr_h, g_probs_h);    cudaGetSymbolAddress((void**)&pr_l, g_probs_l);
    cudaGetSymbolAddress((void**)&at_h, g_attn_h);     cudaGetSymbolAddress((void**)&at_l, g_attn_l);
    cudaGetSymbolAddress((void**)&av_h, g_attnv_h);    cudaGetSymbolAddress((void**)&av_l, g_attnv_l);

    auto cvt = [&](const float* x, bf16* h, bf16* l, long long n) {
        long long n4 = n >> 2;
        cvt_pair_kernel<<<(unsigned)((n4 + 255) / 256), 256>>>(
            (const float4*)x, (__nv_bfloat162*)h, (__nv_bfloat162*)l, n4);
    };
    auto gemm = [&](const bf16* Ahp, const bf16* Alp, const bf16* Bhp, const bf16* Blp,
                    float* Cf, bf16* Chi, bf16* Clo,
                    int M, int N, int K, int lda, int ldb, int ldc,
                    int Z, int Hdim,
                    long long sAb, long long sAh, long long sBb, long long sBh,
                    long long sCb, long long sCh, int mode) {
        dim3 grid((N + 127) / 128, M / 128, Z);
        gemm_mma<<<grid, 128, GSMEM>>>(Ahp, Alp, Bhp, Blp, Cf, Chi, Clo,
                                       N, K, lda, ldb, ldc,
                                       sAb, sAh, sBb, sBh, sCb, sCh, Hdim, mode);
    };

    // operand conversions (weights + hidden)
    cvt(hidden, hid_h, hid_l, (long long)T_TOK * DMODEL);
    cvt(w_qa,   wqa_h, wqa_l, (long long)QLORA * DMODEL);
    cvt(w_kva,  wkva_h, wkva_l, (long long)CDIM * DMODEL);
    cvt(w_qb,   wqb_h, wqb_l, (long long)(NHEAD*DN) * QLORA);
    cvt(w_qrope,wqr_h, wqr_l, (long long)(NHEAD*DR) * QLORA);
    cvt(w_o,    wo_h,  wo_l,  (long long)DMODEL * (NHEAD*DV));
    cvt(w_kvb + (size_t)NHEAD * DN * KVLORA, vup_h, vup_l, (long long)NHEAD * DV * KVLORA);
    transpose_kup_kernel<<<(NHEAD * KVLORA * DN + 255) / 256, 256>>>(w_kvb);
    rope_tab_kernel<<<(SEQ * 32 + 255) / 256, 256>>>(pos);

    // 1. q_mixed = hidden @ w_qa^T ; LN -> qlat pair
    gemm(hid_h, hid_l, wqa_h, wqa_l, q_mixed, nullptr, nullptr,
         T_TOK, QLORA, DMODEL, DMODEL, DMODEL, QLORA, 1, 1, 0,0,0,0,0,0, 0);
    ln_pair_kernel<<<T_TOK, 256>>>(q_mixed, qlat_h, qlat_l, ln_qa_g, ln_qa_b, QLORA, QLORA, QLORA);

    // 2. kv_mixed = hidden @ w_kva^T ; LN -> kfull[:, :512] pair ; rope_k -> [:,512:]
    gemm(hid_h, hid_l, wkva_h, wkva_l, kv_mixed, nullptr, nullptr,
         T_TOK, CDIM, DMODEL, DMODEL, DMODEL, CDIM, 1, 1, 0,0,0,0,0,0, 0);
    ln_pair_kernel<<<T_TOK, 256>>>(kv_mixed, kfull_h, kfull_l, ln_kva_g, ln_kva_b, KVLORA, CDIM, CDIM);
    rope_k_kernel<<<(T_TOK * 32 + 255) / 256, 256>>>();

    // 3. q_nope pair ; q_rope f32 -> rope_q -> qfull pair
    gemm(qlat_h, qlat_l, wqb_h, wqb_l, nullptr, qnope_h, qnope_l,
         T_TOK, NHEAD*DN, QLORA, QLORA, QLORA, NHEAD*DN, 1, 1, 0,0,0,0,0,0, 1);
    gemm(qlat_h, qlat_l, wqr_h, wqr_l, q_rope, nullptr, nullptr,
         T_TOK, NHEAD*DR, QLORA, QLORA, QLORA, NHEAD*DR, 1, 1, 0,0,0,0,0,0, 0);
    rope_q_kernel<<<(T_TOK * NHEAD * 32 + 255) / 256, 256>>>();

    // 4. absorb: qfull[:, h, :512] = q_nope_h @ kupT[h]^T
    gemm(qnope_h, qnope_l, kupT_h, kupT_l, nullptr, qfull_h, qfull_l,
         T_TOK, KVLORA, DN, NHEAD*DN, DN, QF_LD, NHEAD, NHEAD,
         0, DN, 0, (long long)KVLORA * DN, 0, CDIM, 1);

    // 5. kv_latT pair
    transpose_kv_kernel<<<(BATCH * KVLORA * SEQ + 255) / 256, 256>>>();

    // 6. scores = qfull @ kfull^T  (f32)
    gemm(qfull_h, qfull_l, kfull_h, kfull_l, scores, nullptr, nullptr,
         SEQ, SEQ, CDIM, QF_LD, CDIM, SEQ, BATCH * NHEAD, NHEAD,
         (long long)SEQ * QF_LD, CDIM,
         (long long)SEQ * CDIM, 0,
         (long long)NHEAD * SEQ * SEQ, (long long)SEQ * SEQ, 0);

    // 7. softmax -> probs pair
    float scale = (float)(1.0 / sqrt((double)(DN + DR)));
    softmax_pair_kernel<<<BATCH * NHEAD * SEQ, 256>>>(scores, pr_h, pr_l, scale);

    // 8. attn = probs @ kv_latT^T  (pair epilogue)
    gemm(pr_h, pr_l, kvlT_h, kvlT_l, nullptr, at_h, at_l,
         SEQ, KVLORA, SEQ, SEQ, SEQ, KVLORA, BATCH * NHEAD, NHEAD,
         (long long)NHEAD * SEQ * SEQ, (long long)SEQ * SEQ,
         (long long)KVLORA * SEQ, 0,
         (long long)NHEAD * SEQ * KVLORA, (long long)SEQ * KVLORA, 1);

    // 9. attn_v = attn @ v_up^T  (pair epilogue, strided into [b,s,h*DV])
    gemm(at_h, at_l, vup_h, vup_l, nullptr, av_h, av_l,
         SEQ, DV, KVLORA, KVLORA, KVLORA, NHEAD*DV, BATCH * NHEAD, NHEAD,
         (long long)NHEAD * SEQ * KVLORA, (long long)SEQ * KVLORA,
         0, (long long)DV * KVLORA,
         (long long)SEQ * (NHEAD*DV), DV, 1);

    // 10. out = attn_v @ w_o^T  (f32)
    gemm(av_h, av_l, wo_h, wo_l, out, nullptr, nullptr,
         T_TOK, DMODEL, NHEAD*DV, NHEAD*DV, NHEAD*DV, DMODEL, 1, 1,
         0,0,0,0,0,0, 0);
}

// round 10
// speedup vs baseline: 1.7914x; 1.7914x over previous
#include <cuda_runtime.h>
#include <cuda_bf16.h>
#include <cuda_fp16.h>
#include <math.h>
#include <stdint.h>

// ---------------- problem constants ----------------
#define BATCH   2
#define SEQ     2048
#define T_TOK   4096
#define DMODEL  2048
#define NHEAD   16
#define QLORA   1536
#define KVLORA  512
#define DN      128
#define DR      64
#define DV      128
#define CDIM    576
#define QF_LD   (NHEAD*CDIM)   // 9216

typedef __nv_bfloat16 bf16;

// ---------------- scratch (static device memory) ----------------
__device__ float g_q_mixed [(size_t)T_TOK * QLORA];
__device__ float g_kv_mixed[(size_t)T_TOK * CDIM];
__device__ float g_q_rope  [(size_t)T_TOK * (NHEAD*DR)];
__device__ float g_scores  [(size_t)BATCH * NHEAD * SEQ * SEQ];

__device__ bf16 g_hidden_h [(size_t)T_TOK * DMODEL];
__device__ bf16 g_hidden_l [(size_t)T_TOK * DMODEL];
__device__ bf16 g_wqa_h    [(size_t)QLORA * DMODEL];
__device__ bf16 g_wqa_l    [(size_t)QLORA * DMODEL];
__device__ bf16 g_wkva_h   [(size_t)CDIM * DMODEL];
__device__ bf16 g_wkva_l   [(size_t)CDIM * DMODEL];
__device__ bf16 g_wqb_h    [(size_t)(NHEAD*DN) * QLORA];
__device__ bf16 g_wqb_l    [(size_t)(NHEAD*DN) * QLORA];
__device__ bf16 g_wqr_h    [(size_t)(NHEAD*DR) * QLORA];
__device__ bf16 g_wqr_l    [(size_t)(NHEAD*DR) * QLORA];
__device__ bf16 g_wo_h     [(size_t)DMODEL * (NHEAD*DV)];
__device__ bf16 g_wo_l     [(size_t)DMODEL * (NHEAD*DV)];
__device__ bf16 g_kupT_h   [(size_t)NHEAD * KVLORA * DN];
__device__ bf16 g_kupT_l   [(size_t)NHEAD * KVLORA * DN];
__device__ bf16 g_vup_h    [(size_t)NHEAD * DV * KVLORA];
__device__ bf16 g_vup_l    [(size_t)NHEAD * DV * KVLORA];
__device__ bf16 g_qlat_h   [(size_t)T_TOK * QLORA];
__device__ bf16 g_qlat_l   [(size_t)T_TOK * QLORA];
__device__ bf16 g_qnope_h  [(size_t)T_TOK * (NHEAD*DN)];
__device__ bf16 g_qnope_l  [(size_t)T_TOK * (NHEAD*DN)];
__device__ bf16 g_attn_h   [(size_t)BATCH * NHEAD * SEQ * KVLORA];
__device__ bf16 g_attn_l   [(size_t)BATCH * NHEAD * SEQ * KVLORA];
__device__ bf16 g_attnv_h  [(size_t)T_TOK * (NHEAD*DV)];
__device__ bf16 g_attnv_l  [(size_t)T_TOK * (NHEAD*DV)];

// fp16 single-precision operands for attention GEMMs
__device__ __half g_qfull_f16 [(size_t)T_TOK * QF_LD];
__device__ __half g_kfull_f16 [(size_t)T_TOK * CDIM];
__device__ __half g_kvlatT_f16[(size_t)BATCH * KVLORA * SEQ];
__device__ __half g_probs_f16 [(size_t)BATCH * NHEAD * SEQ * SEQ];

__device__ float g_cos[SEQ * 32];
__device__ float g_sin[SEQ * 32];

// ---------------- helpers ----------------
__device__ __forceinline__ uint32_t smem_u32(const void* p) {
    uint32_t a;
    asm("{ .reg .u64 t; cvta.to.shared.u64 t, %1; cvt.u32.u64 %0, t; }" : "=r"(a) : "l"(p));
    return a;
}
__device__ __forceinline__ void cpa16(uint32_t dst, const void* src, uint32_t sz) {
    asm volatile("cp.async.cg.shared.global [%0], [%1], 16, %2;"
                 :: "r"(dst), "l"(src), "r"(sz) : "memory");
}
__device__ __forceinline__ void ldm4(uint32_t* r, uint32_t a) {
    asm volatile("ldmatrix.sync.aligned.m8n8.x4.shared.b16 {%0,%1,%2,%3}, [%4];"
                 : "=r"(r[0]), "=r"(r[1]), "=r"(r[2]), "=r"(r[3]) : "r"(a));
}
__device__ __forceinline__ void mma16816(float* c, const uint32_t* a, const uint32_t* b) {
    asm volatile("mma.sync.aligned.m16n8k16.row.col.f32.bf16.bf16.f32 "
                 "{%0,%1,%2,%3}, {%4,%5,%6,%7}, {%8,%9}, {%0,%1,%2,%3};"
                 : "+f"(c[0]), "+f"(c[1]), "+f"(c[2]), "+f"(c[3])
                 : "r"(a[0]), "r"(a[1]), "r"(a[2]), "r"(a[3]), "r"(b[0]), "r"(b[1]));
}
__device__ __forceinline__ void mma16816h(float* c, const uint32_t* a, const uint32_t* b) {
    asm volatile("mma.sync.aligned.m16n8k16.row.col.f32.f16.f16.f32 "
                 "{%0,%1,%2,%3}, {%4,%5,%6,%7}, {%8,%9}, {%0,%1,%2,%3};"
                 : "+f"(c[0]), "+f"(c[1]), "+f"(c[2]), "+f"(c[3])
                 : "r"(a[0]), "r"(a[1]), "r"(a[2]), "r"(a[3]), "r"(b[0]), "r"(b[1]));
}

// ================ split-bf16 3-pass NT GEMM (projections) ================
// C(MxN) = (Ah+Al)(MxK) * (Bh+Bl)(NxK)^T (drop lo*lo).  K%32==0, M%128==0.
// 256 threads, 8 warps of 64x32.  mode 0: f32 out; 1: bf16 pair; 2: fp16.
#define GSMEM (2 * 32768 + 1024)

__global__ void __launch_bounds__(256, 2)
gemm_mma(const bf16* __restrict__ Ah, const bf16* __restrict__ Al,
         const bf16* __restrict__ Bh, const bf16* __restrict__ Bl,
         float* __restrict__ Cf, bf16* __restrict__ Chi, bf16* __restrict__ Clo,
         __half* __restrict__ Chf,
         int N, int K, int lda, int ldb, int ldc,
         long long sAb, long long sAh_, long long sBb, long long sBh_,
         long long sCb, long long sCh_, int Hdim, int mode)
{
    extern __shared__ char smraw[];
    const uint32_t sbase = (smem_u32(smraw) + 1023) & ~1023u;

    const int tid  = threadIdx.x;
    const int lane = tid & 31;
    const int warp = tid >> 5;
    const int wm = (warp >> 2) * 64;
    const int wn = (warp & 3) * 32;

    const int z  = blockIdx.z;
    const int zb = z / Hdim, zh = z - zb * Hdim;
    const long long aoff = (long long)zb * sAb + (long long)zh * sAh_;
    const long long boff = (long long)zb * sBb + (long long)zh * sBh_;
    Ah += aoff; Al += aoff; Bh += boff; Bl += boff;

    const int m0 = blockIdx.y * 128;
    const int n0 = blockIdx.x * 128;
    const int KT = K >> 5;

    const int lr = tid >> 1;
    const int lh = tid & 1;
    const bf16* pA = (lh ? Al : Ah) + (long long)(m0 + lr) * lda;
    const int brow = n0 + lr;
    const uint32_t bsz = (brow < N) ? 16u : 0u;
    const bf16* pB = (lh ? Bl : Bh) + (long long)((brow < N) ? brow : 0) * ldb;
    uint32_t dOff[4];
    #pragma unroll
    for (int c2 = 0; c2 < 4; c2++)
        dOff[c2] = (uint32_t)(lr * 128 + ((((lh << 2) | c2) ^ (lr & 7)) << 4));

    const int rowA = wm + (lane & 15);
    const uint32_t aAoff = (uint32_t)rowA * 128;
    const int s4  = lane >> 4;
    const int e7A = rowA & 7;
    const int rowB = wn + ((lane >> 4) << 3) + (lane & 7);
    const uint32_t aBoff = 16384u + (uint32_t)rowB * 128;
    const int sB1 = (lane >> 3) & 1;
    const int e7B = lane & 7;

    float C[4][4][4];
    #pragma unroll
    for (int a = 0; a < 4; a++)
        #pragma unroll
        for (int b = 0; b < 4; b++)
            #pragma unroll
            for (int c = 0; c < 4; c++) C[a][b][c] = 0.f;

    {
        const uint32_t sa = sbase;
        #pragma unroll
        for (int c2 = 0; c2 < 4; c2++) {
            cpa16(sa + dOff[c2],          pA + c2 * 8, 16u);
            cpa16(sa + 16384u + dOff[c2], pB + c2 * 8, bsz);
        }
        asm volatile("cp.async.commit_group;" ::: "memory");
    }

    for (int t = 0; t < KT; t++) {
        const int s = t & 1;
        asm volatile("cp.async.wait_group 0;" ::: "memory");
        __syncthreads();
        if (t + 1 < KT) {
            const uint32_t sa = sbase + (uint32_t)(1 - s) * 32768u;
            const int kb = (t + 1) << 5;
            #pragma unroll
            for (int c2 = 0; c2 < 4; c2++) {
                cpa16(sa + dOff[c2],          pA + kb + c2 * 8, 16u);
                cpa16(sa + 16384u + dOff[c2], pB + kb + c2 * 8, bsz);
            }
            asm volatile("cp.async.commit_group;" ::: "memory");
        }
        const uint32_t st = sbase + (uint32_t)s * 32768u;
        #pragma unroll
        for (int g = 0; g < 2; g++) {
            uint32_t Af[2][4][4];
            uint32_t Bf[2][4][2];
            #pragma unroll
            for (int hl = 0; hl < 2; hl++) {
                const uint32_t posA = (uint32_t)((((hl << 2) | (g << 1) | s4) ^ e7A) << 4);
                #pragma unroll
                for (int mt = 0; mt < 4; mt++)
                    ldm4(Af[hl][mt], st + aAoff + mt * 2048u + posA);
                const uint32_t posB = (uint32_t)((((hl << 2) | (g << 1) | sB1) ^ e7B) << 4);
                #pragma unroll
                for (int ntp = 0; ntp < 2; ntp++) {
                    uint32_t r[4];
                    ldm4(r, st + aBoff + ntp * 2048u + posB);
                    Bf[hl][2 * ntp][0] = r[0]; Bf[hl][2 * ntp][1] = r[1];
                    Bf[hl][2 * ntp + 1][0] = r[2]; Bf[hl][2 * ntp + 1][1] = r[3];
                }
            }
            #pragma unroll
            for (int mt = 0; mt < 4; mt++)
                #pragma unroll
                for (int nt = 0; nt < 4; nt++) {
                    mma16816(C[mt][nt], Af[0][mt], Bf[0][nt]);
                    mma16816(C[mt][nt], Af[0][mt], Bf[1][nt]);
                    mma16816(C[mt][nt], Af[1][mt], Bf[0][nt]);
                }
        }
        __syncthreads();
    }

    const long long cz = (long long)zb * sCb + (long long)zh * sCh_;
    #pragma unroll
    for (int mt = 0; mt < 4; mt++) {
        const int rbase = m0 + wm + mt * 16 + (lane >> 2);
        #pragma unroll
        for (int i = 0; i < 2; i++) {
            const long long ro = (long long)(rbase + 8 * i) * ldc + cz;
            #pragma unroll
            for (int nt = 0; nt < 4; nt++) {
                const int col = n0 + wn + nt * 8 + ((lane & 3) << 1);
                if (col < N) {
                    const float v0 = C[mt][nt][2 * i];
                    const float v1 = C[mt][nt][2 * i + 1];
                    if (mode == 0) {
                        *reinterpret_cast<float2*>(Cf + ro + col) = make_float2(v0, v1);
                    } else if (mode == 1) {
                        bf16 h0 = __float2bfloat16(v0);
                        bf16 h1 = __float2bfloat16(v1);
                        bf16 l0 = __float2bfloat16(v0 - __bfloat162float(h0));
                        bf16 l1 = __float2bfloat16(v1 - __bfloat162float(h1));
                        *reinterpret_cast<__nv_bfloat162*>(Chi + ro + col) =
                            __nv_bfloat162(h0, h1);
                        *reinterpret_cast<__nv_bfloat162*>(Clo + ro + col) =
                            __nv_bfloat162(l0, l1);
                    } else {
                        *reinterpret_cast<__half2*>(Chf + ro + col) =
                            __floats2half2_rn(v0, v1);
                    }
                }
            }
        }
    }
}

// ================ fp16 single-pass NT GEMM (attention) ================
// C(MxN) = A(MxK) * B(NxK)^T, fp16 operands, fp32 accum.  K%64==0, M%128==0.
// 256 threads, 8 warps of 64x32, K-tile 64 (128B rows), 2-stage cp.async.
// mode 0: f32 out; 1: bf16 pair out.
#define GSMEM_H (2 * 32768 + 1024)

__global__ void __launch_bounds__(256, 2)
gemm_h(const __half* __restrict__ A, const __half* __restrict__ B,
       float* __restrict__ Cf, bf16* __restrict__ Chi, bf16* __restrict__ Clo,
       int N, int K, int lda, int ldb, int ldc,
       long long sAb, long long sAh_, long long sBb, long long sBh_,
       long long sCb, long long sCh_, int Hdim, int mode)
{
    extern __shared__ char smraw[];
    const uint32_t sbase = (smem_u32(smraw) + 1023) & ~1023u;

    const int tid  = threadIdx.x;
    const int lane = tid & 31;
    const int warp = tid >> 5;
    const int wm = (warp >> 2) * 64;
    const int wn = (warp & 3) * 32;

    const int z  = blockIdx.z;
    const int zb = z / Hdim, zh = z - zb * Hdim;
    A += (long long)zb * sAb + (long long)zh * sAh_;
    B += (long long)zb * sBb + (long long)zh * sBh_;

    const int m0 = blockIdx.y * 128;
    const int n0 = blockIdx.x * 128;
    const int KT = K >> 6;

    // producer: 128B row = 64 halfs of contiguous K; thread covers 4 chunks
    const int lr = tid >> 1;
    const int lh = tid & 1;
    const __half* pA = A + (long long)(m0 + lr) * lda;
    const int brow = n0 + lr;
    const uint32_t bsz = (brow < N) ? 16u : 0u;
    const __half* pB = B + (long long)((brow < N) ? brow : 0) * ldb;
    uint32_t dOff[4];
    #pragma unroll
    for (int c2 = 0; c2 < 4; c2++)
        dOff[c2] = (uint32_t)(lr * 128 + ((((lh << 2) | c2) ^ (lr & 7)) << 4));

    const int rowA = wm + (lane & 15);
    const uint32_t aAoff = (uint32_t)rowA * 128;
    const int s4  = lane >> 4;
    const int e7A = rowA & 7;
    const int rowB = wn + ((lane >> 4) << 3) + (lane & 7);
    const uint32_t aBoff = 16384u + (uint32_t)rowB * 128;
    const int sB1 = (lane >> 3) & 1;
    const int e7B = lane & 7;

    float C[4][4][4];
    #pragma unroll
    for (int a = 0; a < 4; a++)
        #pragma unroll
        for (int b = 0; b < 4; b++)
            #pragma unroll
            for (int c = 0; c < 4; c++) C[a][b][c] = 0.f;

    {
        const uint32_t sa = sbase;
        #pragma unroll
        for (int c2 = 0; c2 < 4; c2++) {
            cpa16(sa + dOff[c2],          pA + ((lh << 2) | c2) * 8, 16u);
            cpa16(sa + 16384u + dOff[c2], pB + ((lh << 2) | c2) * 8, bsz);
        }
        asm volatile("cp.async.commit_group;" ::: "memory");
    }

    for (int t = 0; t < KT; t++) {
        const int s = t & 1;
        asm volatile("cp.async.wait_group 0;" ::: "memory");
        __syncthreads();
        if (t + 1 < KT) {
            const uint32_t sa = sbase + (uint32_t)(1 - s) * 32768u;
            const int kb = (t + 1) << 6;
            #pragma unroll
            for (int c2 = 0; c2 < 4; c2++) {
                cpa16(sa + dOff[c2],          pA + kb + ((lh << 2) | c2) * 8, 16u);
                cpa16(sa + 16384u + dOff[c2], pB + kb + ((lh << 2) | c2) * 8, bsz);
            }
            asm volatile("cp.async.commit_group;" ::: "memory");
        }
        const uint32_t st = sbase + (uint32_t)s * 32768u;
        #pragma unroll
        for (int g = 0; g < 4; g++) {
            uint32_t Af[4][4];
            uint32_t Bf[4][2];
            const uint32_t posA = (uint32_t)((((g << 1) | s4) ^ e7A) << 4);
            #pragma unroll
            for (int mt = 0; mt < 4; mt++)
                ldm4(Af[mt], st + aAoff + mt * 2048u + posA);
            const uint32_t posB = (uint32_t)((((g << 1) | sB1) ^ e7B) << 4);
            #pragma unroll
            for (int ntp = 0; ntp < 2; ntp++) {
                uint32_t r[4];
                ldm4(r, st + aBoff + ntp * 2048u + posB);
                Bf[2 * ntp][0] = r[0]; Bf[2 * ntp][1] = r[1];
                Bf[2 * ntp + 1][0] = r[2]; Bf[2 * ntp + 1][1] = r[3];
            }
            #pragma unroll
            for (int mt = 0; mt < 4; mt++)
                #pragma unroll
                for (int nt = 0; nt < 4; nt++)
                    mma16816h(C[mt][nt], Af[mt], Bf[nt]);
        }
        __syncthreads();
    }

    const long long cz = (long long)zb * sCb + (long long)zh * sCh_;
    #pragma unroll
    for (int mt = 0; mt < 4; mt++) {
        const int rbase = m0 + wm + mt * 16 + (lane >> 2);
        #pragma unroll
        for (int i = 0; i < 2; i++) {
            const long long ro = (long long)(rbase + 8 * i) * ldc + cz;
            #pragma unroll
            for (int nt = 0; nt < 4; nt++) {
                const int col = n0 + wn + nt * 8 + ((lane & 3) << 1);
                if (col < N) {
                    const float v0 = C[mt][nt][2 * i];
                    const float v1 = C[mt][nt][2 * i + 1];
                    if (mode == 0) {
                        *reinterpret_cast<float2*>(Cf + ro + col) = make_float2(v0, v1);
                    } else {
                        bf16 h0 = __float2bfloat16(v0);
                        bf16 h1 = __float2bfloat16(v1);
                        bf16 l0 = __float2bfloat16(v0 - __bfloat162float(h0));
                        bf16 l1 = __float2bfloat16(v1 - __bfloat162float(h1));
                        *reinterpret_cast<__nv_bfloat162*>(Chi + ro + col) =
                            __nv_bfloat162(h0, h1);
                        *reinterpret_cast<__nv_bfloat162*>(Clo + ro + col) =
                            __nv_bfloat162(l0, l1);
                    }
                }
            }
        }
    }
}

// ---------------- elementwise / reduction kernels ----------------
__device__ __forceinline__ void split_store(float v, bf16* hi, bf16* lo, size_t i) {
    bf16 h = __float2bfloat16(v);
    hi[i] = h;
    lo[i] = __float2bfloat16(v - __bfloat162float(h));
}
__device__ __forceinline__ __nv_bfloat162 hi2_of(float a, float b) {
    return __nv_bfloat162(__float2bfloat16(a), __float2bfloat16(b));
}
__device__ __forceinline__ __nv_bfloat162 lo2_of(float a, float b) {
    bf16 ha = __float2bfloat16(a), hb = __float2bfloat16(b);
    return __nv_bfloat162(__float2bfloat16(a - __bfloat162float(ha)),
                          __float2bfloat16(b - __bfloat162float(hb)));
}

__global__ void cvt_pair_kernel(const float4* __restrict__ x,
                                __nv_bfloat162* __restrict__ hi2,
                                __nv_bfloat162* __restrict__ lo2, long long n4)
{
    long long i = (long long)blockIdx.x * 256 + threadIdx.x;
    if (i < n4) {
        float4 v = x[i];
        hi2[2 * i]     = hi2_of(v.x, v.y);
        hi2[2 * i + 1] = hi2_of(v.z, v.w);
        lo2[2 * i]     = lo2_of(v.x, v.y);
        lo2[2 * i + 1] = lo2_of(v.z, v.w);
    }
}

__device__ __forceinline__ float block_reduce(float v, float* red, bool is_max)
{
    #pragma unroll
    for (int o = 16; o > 0; o >>= 1) {
        float w = __shfl_xor_sync(0xffffffffu, v, o);
        v = is_max ? fmaxf(v, w) : (v + w);
    }
    if ((threadIdx.x & 31) == 0) red[threadIdx.x >> 5] = v;
    __syncthreads();
    float r = red[0];
    #pragma unroll
    for (int i = 1; i < 8; i++) r = is_max ? fmaxf(r, red[i]) : (r + red[i]);
    __syncthreads();
    return r;
}

// LN -> bf16 hi/lo pair (q path)
__global__ __launch_bounds__(256) void ln_pair_kernel(
    const float* x, bf16* yhi, bf16* ylo,
    const float* __restrict__ g, const float* __restrict__ b,
    int L, int ldx, int ldy)
{
    __shared__ float s[QLORA];
    __shared__ float red[8];
    long long row = blockIdx.x;
    const float* xr = x + row * ldx;
    size_t ybase = (size_t)row * ldy;
    int tid = threadIdx.x;

    float part = 0.f;
    for (int i = tid; i < L; i += 256) { float v = xr[i]; s[i] = v; part += v; }
    float mu = block_reduce(part, red, false) / (float)L;
    float p2 = 0.f;
    for (int i = tid; i < L; i += 256) { float d = s[i] - mu; p2 += d * d; }
    float var  = block_reduce(p2, red, false) / (float)L;
    float rstd = rsqrtf(var + 1e-5f);
    for (int i = tid; i < L; i += 256)
        split_store((s[i] - mu) * rstd * g[i] + b[i], yhi, ylo, ybase + i);
}

// LN -> fp16 single (kv path)
__global__ __launch_bounds__(256) void ln_half_kernel(
    const float* x, __half* y,
    const float* __restrict__ g, const float* __restrict__ b,
    int L, int ldx, int ldy)
{
    __shared__ float s[KVLORA];
    __shared__ float red[8];
    long long row = blockIdx.x;
    const float* xr = x + row * ldx;
    size_t ybase = (size_t)row * ldy;
    int tid = threadIdx.x;

    float part = 0.f;
    for (int i = tid; i < L; i += 256) { float v = xr[i]; s[i] = v; part += v; }
    float mu = block_reduce(part, red, false) / (float)L;
    float p2 = 0.f;
    for (int i = tid; i < L; i += 256) { float d = s[i] - mu; p2 += d * d; }
    float var  = block_reduce(p2, red, false) / (float)L;
    float rstd = rsqrtf(var + 1e-5f);
    for (int i = tid; i < L; i += 256)
        y[ybase + i] = __float2half_rn((s[i] - mu) * rstd * g[i] + b[i]);
}

// softmax over SEQ rows -> fp16 single, vectorized IO
__global__ __launch_bounds__(256) void softmax_half_kernel(
    const float* __restrict__ sc, __half* __restrict__ pr, float scale)
{
    __shared__ float red[8];
    const float4* p4 = reinterpret_cast<const float4*>(sc + (long long)blockIdx.x * SEQ);
    size_t obase = (size_t)blockIdx.x * SEQ;
    int tid = threadIdx.x;
    float v[8];
    float4 a = p4[tid], b = p4[tid + 256];
    v[0]=a.x*scale; v[1]=a.y*scale; v[2]=a.z*scale; v[3]=a.w*scale;
    v[4]=b.x*scale; v[5]=b.y*scale; v[6]=b.z*scale; v[7]=b.w*scale;
    float mx = v[0];
    #pragma unroll
    for (int j = 1; j < 8; j++) mx = fmaxf(mx, v[j]);
    mx = block_reduce(mx, red, true);
    float sum = 0.f;
    #pragma unroll
    for (int j = 0; j < 8; j++) { v[j] = __expf(v[j] - mx); sum += v[j]; }
    sum = block_reduce(sum, red, false);
    float inv = 1.0f / sum;
    __half2* o2 = reinterpret_cast<__half2*>(pr + obase);
    #pragma unroll
    for (int j = 0; j < 2; j++) {
        int f4 = tid + j * 256;
        o2[2 * f4]     = __floats2half2_rn(v[4*j] * inv,   v[4*j+1] * inv);
        o2[2 * f4 + 1] = __floats2half2_rn(v[4*j+2] * inv, v[4*j+3] * inv);
    }
}

__global__ void rope_tab_kernel(const int* __restrict__ pos)
{
    int idx = blockIdx.x * blockDim.x + threadIdx.x;
    if (idx >= SEQ * 32) return;
    int s = idx >> 5, i = idx & 31;
    double freq = exp(-((double)(2 * i) / 64.0) * log(10000.0));
    double ang  = (double)pos[s] * freq;
    g_cos[idx] = (float)cos(ang);
    g_sin[idx] = (float)sin(ang);
}

// k_rope: kv_mixed f32 cols [512:576) -> kfull_f16 cols [512:576)
__global__ void rope_k_kernel()
{
    int idx = blockIdx.x * blockDim.x + threadIdx.x;
    if (idx >= T_TOK * 32) return;
    int t = idx >> 5, i = idx & 31;
    int s = t & (SEQ - 1);
    float c  = g_cos[(s << 5) + i];
    float sn = g_sin[(s << 5) + i];
    const float* x = g_kv_mixed + (size_t)t * CDIM + KVLORA;
    float x1 = x[i], x2 = x[i + 32];
    size_t o = (size_t)t * CDIM + KVLORA;
    g_kfull_f16[o + i]      = __float2half_rn(x1 * c  - x2 * sn);
    g_kfull_f16[o + i + 32] = __float2half_rn(x1 * sn + x2 * c);
}

// q_rope f32 -> qfull_f16 at [t, h*576+512 ...]
__global__ void rope_q_kernel()
{
    int idx = blockIdx.x * blockDim.x + threadIdx.x;
    if (idx >= T_TOK * NHEAD * 32) return;
    int t = idx >> 9;
    int rem = idx & 511;
    int h = rem >> 5, i = rem & 31;
    int s = t & (SEQ - 1);
    float c  = g_cos[(s << 5) + i];
    float sn = g_sin[(s << 5) + i];
    const float* x = g_q_rope + (size_t)t * (NHEAD * DR) + h * DR;
    float x1 = x[i], x2 = x[i + 32];
    size_t o = (size_t)t * QF_LD + h * CDIM + KVLORA;
    g_qfull_f16[o + i]      = __float2half_rn(x1 * c  - x2 * sn);
    g_qfull_f16[o + i + 32] = __float2half_rn(x1 * sn + x2 * c);
}

__global__ void transpose_kup_kernel(const float* __restrict__ w_kvb)
{
    int idx = blockIdx.x * blockDim.x + threadIdx.x;
    if (idx >= NHEAD * KVLORA * DN) return;
    int h   = idx >> 16;
    int rem = idx & 65535;
    int r   = rem >> 7;
    int d   = rem & 127;
    split_store(w_kvb[(size_t)((h << 7) + d) * KVLORA + r], g_kupT_h, g_kupT_l, (size_t)idx);
}

// kvlatT_f16[b][r][k] = kfull_f16[(b*SEQ+k)*576 + r]
__global__ void transpose_kv_kernel()
{
    int idx = blockIdx.x * blockDim.x + threadIdx.x;
    if (idx >= BATCH * KVLORA * SEQ) return;
    int b   = idx >> 20;
    int rem = idx & ((1 << 20) - 1);
    int r   = rem >> 11;
    int k   = rem & (SEQ - 1);
    g_kvlatT_f16[idx] = g_kfull_f16[(size_t)((b << 11) + k) * CDIM + r];
}

// ---------------- host ----------------
extern "C" void kernel_launch(void* const* d_in, const int* in_sizes, int n_in,
                              void* d_out, int out_size)
{
    (void)in_sizes; (void)n_in; (void)out_size;
    const float* hidden   = (const float*)d_in[0];
    const float* w_qa     = (const float*)d_in[1];
    const float* ln_qa_g  = (const float*)d_in[2];
    const float* ln_qa_b  = (const float*)d_in[3];
    const float* w_qb     = (const float*)d_in[4];
    const float* w_qrope  = (const float*)d_in[5];
    const float* w_kva    = (const float*)d_in[6];
    const float* ln_kva_g = (const float*)d_in[7];
    const float* ln_kva_b = (const float*)d_in[8];
    const float* w_kvb    = (const float*)d_in[9];
    const float* w_o      = (const float*)d_in[10];
    const int*   pos      = (const int*)d_in[11];
    float* out = (float*)d_out;

    cudaFuncSetAttribute(gemm_mma, cudaFuncAttributeMaxDynamicSharedMemorySize, GSMEM);
    cudaFuncSetAttribute(gemm_h,   cudaFuncAttributeMaxDynamicSharedMemorySize, GSMEM_H);

    float *q_mixed, *kv_mixed, *q_rope, *scores;
    bf16 *hid_h,*hid_l,*wqa_h,*wqa_l,*wkva_h,*wkva_l,*wqb_h,*wqb_l,*wqr_h,*wqr_l,*wo_h,*wo_l;
    bf16 *kupT_h,*kupT_l,*vup_h,*vup_l,*qlat_h,*qlat_l,*qnope_h,*qnope_l;
    bf16 *at_h,*at_l,*av_h,*av_l;
    __half *qfull16,*kfull16,*kvlT16,*probs16;
    cudaGetSymbolAddress((void**)&q_mixed, g_q_mixed);
    cudaGetSymbolAddress((void**)&kv_mixed, g_kv_mixed);
    cudaGetSymbolAddress((void**)&q_rope, g_q_rope);
    cudaGetSymbolAddress((void**)&scores, g_scores);
    cudaGetSymbolAddress((void**)&hid_h, g_hidden_h);  cudaGetSymbolAddress((void**)&hid_l, g_hidden_l);
    cudaGetSymbolAddress((void**)&wqa_h, g_wqa_h);     cudaGetSymbolAddress((void**)&wqa_l, g_wqa_l);
    cudaGetSymbolAddress((void**)&wkva_h, g_wkva_h);   cudaGetSymbolAddress((void**)&wkva_l, g_wkva_l);
    cudaGetSymbolAddress((void**)&wqb_h, g_wqb_h);     cudaGetSymbolAddress((void**)&wqb_l, g_wqb_l);
    cudaGetSymbolAddress((void**)&wqr_h, g_wqr_h);     cudaGetSymbolAddress((void**)&wqr_l, g_wqr_l);
    cudaGetSymbolAddress((void**)&wo_h, g_wo_h);       cudaGetSymbolAddress((void**)&wo_l, g_wo_l);
    cudaGetSymbolAddress((void**)&kupT_h, g_kupT_h);   cudaGetSymbolAddress((void**)&kupT_l, g_kupT_l);
    cudaGetSymbolAddress((void**)&vup_h, g_vup_h);     cudaGetSymbolAddress((void**)&vup_l, g_vup_l);
    cudaGetSymbolAddress((void**)&qlat_h, g_qlat_h);   cudaGetSymbolAddress((void**)&qlat_l, g_qlat_l);
    cudaGetSymbolAddress((void**)&qnope_h, g_qnope_h); cudaGetSymbolAddress((void**)&qnope_l, g_qnope_l);
    cudaGetSymbolAddress((void**)&at_h, g_attn_h);     cudaGetSymbolAddress((void**)&at_l, g_attn_l);
    cudaGetSymbolAddress((void**)&av_h, g_attnv_h);    cudaGetSymbolAddress((void**)&av_l, g_attnv_l);
    cudaGetSymbolAddress((void**)&qfull16, g_qfull_f16);
    cudaGetSymbolAddress((void**)&kfull16, g_kfull_f16);
    cudaGetSymbolAddress((void**)&kvlT16, g_kvlatT_f16);
    cudaGetSymbolAddress((void**)&probs16, g_probs_f16);

    auto cvt = [&](const float* x, bf16* h, bf16* l, long long n) {
        long long n4 = n >> 2;
        cvt_pair_kernel<<<(unsigned)((n4 + 255) / 256), 256>>>(
            (const float4*)x, (__nv_bfloat162*)h, (__nv_bfloat162*)l, n4);
    };
    auto gemm = [&](const bf16* Ahp, const bf16* Alp, const bf16* Bhp, const bf16* Blp,
                    float* Cf, bf16* Chi, bf16* Clo, __half* Chf,
                    int M, int N, int K, int lda, int ldb, int ldc,
                    int Z, int Hdim,
                    long long sAb, long long sAh, long long sBb, long long sBh,
                    long long sCb, long long sCh, int mode) {
        dim3 grid((N + 127) / 128, M / 128, Z);
        gemm_mma<<<grid, 256, GSMEM>>>(Ahp, Alp, Bhp, Blp, Cf, Chi, Clo, Chf,
                                       N, K, lda, ldb, ldc,
                                       sAb, sAh, sBb, sBh, sCb, sCh, Hdim, mode);
    };
    auto gemmh = [&](const __half* Ap, const __half* Bp,
                     float* Cf, bf16* Chi, bf16* Clo,
                     int M, int N, int K, int lda, int ldb, int ldc,
                     int Z, int Hdim,
                     long long sAb, long long sAh, long long sBb, long long sBh,
                     long long sCb, long long sCh, int mode) {
        dim3 grid((N + 127) / 128, M / 128, Z);
        gemm_h<<<grid, 256, GSMEM_H>>>(Ap, Bp, Cf, Chi, Clo,
                                       N, K, lda, ldb, ldc,
                                       sAb, sAh, sBb, sBh, sCb, sCh, Hdim, mode);
    };

    // operand conversions
    cvt(hidden, hid_h, hid_l, (long long)T_TOK * DMODEL);
    cvt(w_qa,   wqa_h, wqa_l, (long long)QLORA * DMODEL);
    cvt(w_kva,  wkva_h, wkva_l, (long long)CDIM * DMODEL);
    cvt(w_qb,   wqb_h, wqb_l, (long long)(NHEAD*DN) * QLORA);
    cvt(w_qrope,wqr_h, wqr_l, (long long)(NHEAD*DR) * QLORA);
    cvt(w_o,    wo_h,  wo_l,  (long long)DMODEL * (NHEAD*DV));
    cvt(w_kvb + (size_t)NHEAD * DN * KVLORA, vup_h, vup_l, (long long)NHEAD * DV * KVLORA);
    transpose_kup_kernel<<<(NHEAD * KVLORA * DN + 255) / 256, 256>>>(w_kvb);
    rope_tab_kernel<<<(SEQ * 32 + 255) / 256, 256>>>(pos);

    // 1. q_mixed = hidden @ w_qa^T ; LN -> qlat pair
    gemm(hid_h, hid_l, wqa_h, wqa_l, q_mixed, nullptr, nullptr, nullptr,
         T_TOK, QLORA, DMODEL, DMODEL, DMODEL, QLORA, 1, 1, 0,0,0,0,0,0, 0);
    ln_pair_kernel<<<T_TOK, 256>>>(q_mixed, qlat_h, qlat_l, ln_qa_g, ln_qa_b, QLORA, QLORA, QLORA);

    // 2. kv_mixed = hidden @ w_kva^T ; LN -> kfull_f16[:, :512] ; rope_k -> [:,512:]
    gemm(hid_h, hid_l, wkva_h, wkva_l, kv_mixed, nullptr, nullptr, nullptr,
         T_TOK, CDIM, DMODEL, DMODEL, DMODEL, CDIM, 1, 1, 0,0,0,0,0,0, 0);
    ln_half_kernel<<<T_TOK, 256>>>(kv_mixed, kfull16, ln_kva_g, ln_kva_b, KVLORA, CDIM, CDIM);
    rope_k_kernel<<<(T_TOK * 32 + 255) / 256, 256>>>();

    // 3. q_nope pair ; q_rope f32 -> rope_q -> qfull_f16
    gemm(qlat_h, qlat_l, wqb_h, wqb_l, nullptr, qnope_h, qnope_l, nullptr,
         T_TOK, NHEAD*DN, QLORA, QLORA, QLORA, NHEAD*DN, 1, 1, 0,0,0,0,0,0, 1);
    gemm(qlat_h, qlat_l, wqr_h, wqr_l, q_rope, nullptr, nullptr, nullptr,
         T_TOK, NHEAD*DR, QLORA, QLORA, QLORA, NHEAD*DR, 1, 1, 0,0,0,0,0,0, 0);
    rope_q_kernel<<<(T_TOK * NHEAD * 32 + 255) / 256, 256>>>();

    // 4. absorb: qfull_f16[:, h, :512] = q_nope_h @ kupT[h]^T (fp16 epilogue)
    gemm(qnope_h, qnope_l, kupT_h, kupT_l, nullptr, nullptr, nullptr, qfull16,
         T_TOK, KVLORA, DN, NHEAD*DN, DN, QF_LD, NHEAD, NHEAD,
         0, DN, 0, (long long)KVLORA * DN, 0, CDIM, 2);

    // 5. kvlatT_f16
    transpose_kv_kernel<<<(BATCH * KVLORA * SEQ + 255) / 256, 256>>>();

    // 6. scores = qfull @ kfull^T  (fp16 single pass, f32 out)
    gemmh(qfull16, kfull16, scores, nullptr, nullptr,
          SEQ, SEQ, CDIM, QF_LD, CDIM, SEQ, BATCH * NHEAD, NHEAD,
          (long long)SEQ * QF_LD, CDIM,
          (long long)SEQ * CDIM, 0,
          (long long)NHEAD * SEQ * SEQ, (long long)SEQ * SEQ, 0);

    // 7. softmax -> probs fp16
    float scale = (float)(1.0 / sqrt((double)(DN + DR)));
    softmax_half_kernel<<<BATCH * NHEAD * SEQ, 256>>>(scores, probs16, scale);

    // 8. attn = probs @ kvlatT^T  (fp16 single pass, bf16-pair out)
    gemmh(probs16, kvlT16, nullptr, at_h, at_l,
          SEQ, KVLORA, SEQ, SEQ, SEQ, KVLORA, BATCH * NHEAD, NHEAD,
          (long long)NHEAD * SEQ * SEQ, (long long)SEQ * SEQ,
          (long long)KVLORA * SEQ, 0,
          (long long)NHEAD * SEQ * KVLORA, (long long)SEQ * KVLORA, 1);

    // 9. attn_v = attn @ v_up^T  (split-bf16, pair out strided into [b,s,h*DV])
    gemm(at_h, at_l, vup_h, vup_l, nullptr, av_h, av_l, nullptr,
         SEQ, DV, KVLORA, KVLORA, KVLORA, NHEAD*DV, BATCH * NHEAD, NHEAD,
         (long long)NHEAD * SEQ * KVLORA, (long long)SEQ * KVLORA,
         0, (long long)DV * KVLORA,
         (long long)SEQ * (NHEAD*DV), DV, 1);

    // 10. out = attn_v @ w_o^T  (split-bf16, f32 out)
    gemm(av_h, av_l, wo_h, wo_l, out, nullptr, nullptr, nullptr,
         T_TOK, DMODEL, NHEAD*DV, NHEAD*DV, NHEAD*DV, DMODEL, 1, 1,
         0,0,0,0,0,0, 0);
}

// round 11
// speedup vs baseline: 2.9992x; 1.6742x over previous
#include <cuda_runtime.h>
#include <cuda_fp16.h>
#include <math.h>
#include <stdint.h>

// ---------------- problem constants ----------------
#define BATCH   2
#define SEQ     2048
#define T_TOK   4096
#define DMODEL  2048
#define NHEAD   16
#define QLORA   1536
#define KVLORA  512
#define DN      128
#define DR      64
#define DV      128
#define CDIM    576
#define QF_LD   (NHEAD*CDIM)   // 9216

// ---------------- scratch (static device memory) ----------------
__device__ float g_q_mixed [(size_t)T_TOK * QLORA];
__device__ float g_kv_mixed[(size_t)T_TOK * CDIM];
__device__ float g_q_rope  [(size_t)T_TOK * (NHEAD*DR)];
__device__ float g_scores  [(size_t)BATCH * NHEAD * SEQ * SEQ];

__device__ __half g_hidden [(size_t)T_TOK * DMODEL];
__device__ __half g_wqa    [(size_t)QLORA * DMODEL];
__device__ __half g_wkva   [(size_t)CDIM * DMODEL];
__device__ __half g_wqb    [(size_t)(NHEAD*DN) * QLORA];
__device__ __half g_wqr    [(size_t)(NHEAD*DR) * QLORA];
__device__ __half g_wo     [(size_t)DMODEL * (NHEAD*DV)];
__device__ __half g_kupT   [(size_t)NHEAD * KVLORA * DN];
__device__ __half g_vup    [(size_t)NHEAD * DV * KVLORA];
__device__ __half g_qlat   [(size_t)T_TOK * QLORA];
__device__ __half g_qnope  [(size_t)T_TOK * (NHEAD*DN)];
__device__ __half g_qfull  [(size_t)T_TOK * QF_LD];
__device__ __half g_kfull  [(size_t)T_TOK * CDIM];
__device__ __half g_kvlatT [(size_t)BATCH * KVLORA * SEQ];
__device__ __half g_probs  [(size_t)BATCH * NHEAD * SEQ * SEQ];
__device__ __half g_attn   [(size_t)BATCH * NHEAD * SEQ * KVLORA];
__device__ __half g_attnv  [(size_t)T_TOK * (NHEAD*DV)];

__device__ float g_cos[SEQ * 32];
__device__ float g_sin[SEQ * 32];

// ---------------- helpers ----------------
__device__ __forceinline__ uint32_t smem_u32(const void* p) {
    uint32_t a;
    asm("{ .reg .u64 t; cvta.to.shared.u64 t, %1; cvt.u32.u64 %0, t; }" : "=r"(a) : "l"(p));
    return a;
}
__device__ __forceinline__ void cpa16(uint32_t dst, const void* src, uint32_t sz) {
    asm volatile("cp.async.cg.shared.global [%0], [%1], 16, %2;"
                 :: "r"(dst), "l"(src), "r"(sz) : "memory");
}
__device__ __forceinline__ void ldm4(uint32_t* r, uint32_t a) {
    asm volatile("ldmatrix.sync.aligned.m8n8.x4.shared.b16 {%0,%1,%2,%3}, [%4];"
                 : "=r"(r[0]), "=r"(r[1]), "=r"(r[2]), "=r"(r[3]) : "r"(a));
}
__device__ __forceinline__ void mma16816h(float* c, const uint32_t* a, const uint32_t* b) {
    asm volatile("mma.sync.aligned.m16n8k16.row.col.f32.f16.f16.f32 "
                 "{%0,%1,%2,%3}, {%4,%5,%6,%7}, {%8,%9}, {%0,%1,%2,%3};"
                 : "+f"(c[0]), "+f"(c[1]), "+f"(c[2]), "+f"(c[3])
                 : "r"(a[0]), "r"(a[1]), "r"(a[2]), "r"(a[3]), "r"(b[0]), "r"(b[1]));
}

// ================ fp16 single-pass NT GEMM ================
// C(MxN) = A(MxK) * B(NxK)^T, fp16 operands, fp32 accum.  K%64==0, M%128==0.
// 256 threads, 8 warps of 64x32, K-tile 64 (128B rows), 2-stage cp.async.
// mode 0: f32 out; 1: fp16 out.
#define GSMEM_H (2 * 32768 + 1024)

__global__ void __launch_bounds__(256, 2)
gemm_h(const __half* __restrict__ A, const __half* __restrict__ B,
       float* __restrict__ Cf, __half* __restrict__ Chf,
       int N, int K, int lda, int ldb, int ldc,
       long long sAb, long long sAh_, long long sBb, long long sBh_,
       long long sCb, long long sCh_, int Hdim, int mode)
{
    extern __shared__ char smraw[];
    const uint32_t sbase = (smem_u32(smraw) + 1023) & ~1023u;

    const int tid  = threadIdx.x;
    const int lane = tid & 31;
    const int warp = tid >> 5;
    const int wm = (warp >> 2) * 64;
    const int wn = (warp & 3) * 32;

    const int z  = blockIdx.z;
    const int zb = z / Hdim, zh = z - zb * Hdim;
    A += (long long)zb * sAb + (long long)zh * sAh_;
    B += (long long)zb * sBb + (long long)zh * sBh_;

    const int m0 = blockIdx.y * 128;
    const int n0 = blockIdx.x * 128;
    const int KT = K >> 6;

    // producer: 128B row = 64 halfs of contiguous K; thread covers 4 chunks
    const int lr = tid >> 1;
    const int lh = tid & 1;
    const __half* pA = A + (long long)(m0 + lr) * lda;
    const int brow = n0 + lr;
    const uint32_t bsz = (brow < N) ? 16u : 0u;
    const __half* pB = B + (long long)((brow < N) ? brow : 0) * ldb;
    uint32_t dOff[4];
    #pragma unroll
    for (int c2 = 0; c2 < 4; c2++)
        dOff[c2] = (uint32_t)(lr * 128 + ((((lh << 2) | c2) ^ (lr & 7)) << 4));

    const int rowA = wm + (lane & 15);
    const uint32_t aAoff = (uint32_t)rowA * 128;
    const int s4  = lane >> 4;
    const int e7A = rowA & 7;
    const int rowB = wn + ((lane >> 4) << 3) + (lane & 7);
    const uint32_t aBoff = 16384u + (uint32_t)rowB * 128;
    const int sB1 = (lane >> 3) & 1;
    const int e7B = lane & 7;

    float C[4][4][4];
    #pragma unroll
    for (int a = 0; a < 4; a++)
        #pragma unroll
        for (int b = 0; b < 4; b++)
            #pragma unroll
            for (int c = 0; c < 4; c++) C[a][b][c] = 0.f;

    {
        const uint32_t sa = sbase;
        #pragma unroll
        for (int c2 = 0; c2 < 4; c2++) {
            cpa16(sa + dOff[c2],          pA + ((lh << 2) | c2) * 8, 16u);
            cpa16(sa + 16384u + dOff[c2], pB + ((lh << 2) | c2) * 8, bsz);
        }
        asm volatile("cp.async.commit_group;" ::: "memory");
    }

    for (int t = 0; t < KT; t++) {
        const int s = t & 1;
        asm volatile("cp.async.wait_group 0;" ::: "memory");
        __syncthreads();
        if (t + 1 < KT) {
            const uint32_t sa = sbase + (uint32_t)(1 - s) * 32768u;
            const int kb = (t + 1) << 6;
            #pragma unroll
            for (int c2 = 0; c2 < 4; c2++) {
                cpa16(sa + dOff[c2],          pA + kb + ((lh << 2) | c2) * 8, 16u);
                cpa16(sa + 16384u + dOff[c2], pB + kb + ((lh << 2) | c2) * 8, bsz);
            }
            asm volatile("cp.async.commit_group;" ::: "memory");
        }
        const uint32_t st = sbase + (uint32_t)s * 32768u;
        #pragma unroll
        for (int g = 0; g < 4; g++) {
            uint32_t Af[4][4];
            uint32_t Bf[4][2];
            const uint32_t posA = (uint32_t)((((g << 1) | s4) ^ e7A) << 4);
            #pragma unroll
            for (int mt = 0; mt < 4; mt++)
                ldm4(Af[mt], st + aAoff + mt * 2048u + posA);
            const uint32_t posB = (uint32_t)((((g << 1) | sB1) ^ e7B) << 4);
            #pragma unroll
            for (int ntp = 0; ntp < 2; ntp++) {
                uint32_t r[4];
                ldm4(r, st + aBoff + ntp * 2048u + posB);
                Bf[2 * ntp][0] = r[0]; Bf[2 * ntp][1] = r[1];
                Bf[2 * ntp + 1][0] = r[2]; Bf[2 * ntp + 1][1] = r[3];
            }
            #pragma unroll
            for (int mt = 0; mt < 4; mt++)
                #pragma unroll
                for (int nt = 0; nt < 4; nt++)
                    mma16816h(C[mt][nt], Af[mt], Bf[nt]);
        }
        __syncthreads();
    }

    const long long cz = (long long)zb * sCb + (long long)zh * sCh_;
    #pragma unroll
    for (int mt = 0; mt < 4; mt++) {
        const int rbase = m0 + wm + mt * 16 + (lane >> 2);
        #pragma unroll
        for (int i = 0; i < 2; i++) {
            const long long ro = (long long)(rbase + 8 * i) * ldc + cz;
            #pragma unroll
            for (int nt = 0; nt < 4; nt++) {
                const int col = n0 + wn + nt * 8 + ((lane & 3) << 1);
                if (col < N) {
                    const float v0 = C[mt][nt][2 * i];
                    const float v1 = C[mt][nt][2 * i + 1];
                    if (mode == 0) {
                        *reinterpret_cast<float2*>(Cf + ro + col) = make_float2(v0, v1);
                    } else {
                        *reinterpret_cast<__half2*>(Chf + ro + col) =
                            __floats2half2_rn(v0, v1);
                    }
                }
            }
        }
    }
}

// ---------------- elementwise / reduction kernels ----------------
__global__ void cvt_half_kernel(const float4* __restrict__ x,
                                __half2* __restrict__ y2, long long n4)
{
    long long i = (long long)blockIdx.x * 256 + threadIdx.x;
    if (i < n4) {
        float4 v = x[i];
        y2[2 * i]     = __floats2half2_rn(v.x, v.y);
        y2[2 * i + 1] = __floats2half2_rn(v.z, v.w);
    }
}

__device__ __forceinline__ float block_reduce(float v, float* red, bool is_max)
{
    #pragma unroll
    for (int o = 16; o > 0; o >>= 1) {
        float w = __shfl_xor_sync(0xffffffffu, v, o);
        v = is_max ? fmaxf(v, w) : (v + w);
    }
    if ((threadIdx.x & 31) == 0) red[threadIdx.x >> 5] = v;
    __syncthreads();
    float r = red[0];
    #pragma unroll
    for (int i = 1; i < 8; i++) r = is_max ? fmaxf(r, red[i]) : (r + red[i]);
    __syncthreads();
    return r;
}

// LN -> fp16 (strided out)
__global__ __launch_bounds__(256) void ln_half_kernel(
    const float* x, __half* y,
    const float* __restrict__ g, const float* __restrict__ b,
    int L, int ldx, int ldy)
{
    __shared__ float s[QLORA];
    __shared__ float red[8];
    long long row = blockIdx.x;
    const float* xr = x + row * ldx;
    size_t ybase = (size_t)row * ldy;
    int tid = threadIdx.x;

    float part = 0.f;
    for (int i = tid; i < L; i += 256) { float v = xr[i]; s[i] = v; part += v; }
    float mu = block_reduce(part, red, false) / (float)L;
    float p2 = 0.f;
    for (int i = tid; i < L; i += 256) { float d = s[i] - mu; p2 += d * d; }
    float var  = block_reduce(p2, red, false) / (float)L;
    float rstd = rsqrtf(var + 1e-5f);
    for (int i = tid; i < L; i += 256)
        y[ybase + i] = __float2half_rn((s[i] - mu) * rstd * g[i] + b[i]);
}

// softmax over SEQ rows -> fp16, vectorized IO
__global__ __launch_bounds__(256) void softmax_half_kernel(
    const float* __restrict__ sc, __half* __restrict__ pr, float scale)
{
    __shared__ float red[8];
    const float4* p4 = reinterpret_cast<const float4*>(sc + (long long)blockIdx.x * SEQ);
    size_t obase = (size_t)blockIdx.x * SEQ;
    int tid = threadIdx.x;
    float v[8];
    float4 a = p4[tid], b = p4[tid + 256];
    v[0]=a.x*scale; v[1]=a.y*scale; v[2]=a.z*scale; v[3]=a.w*scale;
    v[4]=b.x*scale; v[5]=b.y*scale; v[6]=b.z*scale; v[7]=b.w*scale;
    float mx = v[0];
    #pragma unroll
    for (int j = 1; j < 8; j++) mx = fmaxf(mx, v[j]);
    mx = block_reduce(mx, red, true);
    float sum = 0.f;
    #pragma unroll
    for (int j = 0; j < 8; j++) { v[j] = __expf(v[j] - mx); sum += v[j]; }
    sum = block_reduce(sum, red, false);
    float inv = 1.0f / sum;
    __half2* o2 = reinterpret_cast<__half2*>(pr + obase);
    #pragma unroll
    for (int j = 0; j < 2; j++) {
        int f4 = tid + j * 256;
        o2[2 * f4]     = __floats2half2_rn(v[4*j] * inv,   v[4*j+1] * inv);
        o2[2 * f4 + 1] = __floats2half2_rn(v[4*j+2] * inv, v[4*j+3] * inv);
    }
}

__global__ void rope_tab_kernel(const int* __restrict__ pos)
{
    int idx = blockIdx.x * blockDim.x + threadIdx.x;
    if (idx >= SEQ * 32) return;
    int s = idx >> 5, i = idx & 31;
    double freq = exp(-((double)(2 * i) / 64.0) * log(10000.0));
    double ang  = (double)pos[s] * freq;
    g_cos[idx] = (float)cos(ang);
    g_sin[idx] = (float)sin(ang);
}

// k_rope: kv_mixed f32 cols [512:576) -> kfull cols [512:576)
__global__ void rope_k_kernel()
{
    int idx = blockIdx.x * blockDim.x + threadIdx.x;
    if (idx >= T_TOK * 32) return;
    int t = idx >> 5, i = idx & 31;
    int s = t & (SEQ - 1);
    float c  = g_cos[(s << 5) + i];
    float sn = g_sin[(s << 5) + i];
    const float* x = g_kv_mixed + (size_t)t * CDIM + KVLORA;
    float x1 = x[i], x2 = x[i + 32];
    size_t o = (size_t)t * CDIM + KVLORA;
    g_kfull[o + i]      = __float2half_rn(x1 * c  - x2 * sn);
    g_kfull[o + i + 32] = __float2half_rn(x1 * sn + x2 * c);
}

// q_rope f32 -> qfull at [t, h*576+512 ...]
__global__ void rope_q_kernel()
{
    int idx = blockIdx.x * blockDim.x + threadIdx.x;
    if (idx >= T_TOK * NHEAD * 32) return;
    int t = idx >> 9;
    int rem = idx & 511;
    int h = rem >> 5, i = rem & 31;
    int s = t & (SEQ - 1);
    float c  = g_cos[(s << 5) + i];
    float sn = g_sin[(s << 5) + i];
    const float* x = g_q_rope + (size_t)t * (NHEAD * DR) + h * DR;
    float x1 = x[i], x2 = x[i + 32];
    size_t o = (size_t)t * QF_LD + h * CDIM + KVLORA;
    g_qfull[o + i]      = __float2half_rn(x1 * c  - x2 * sn);
    g_qfull[o + i + 32] = __float2half_rn(x1 * sn + x2 * c);
}

__global__ void transpose_kup_kernel(const float* __restrict__ w_kvb)
{
    int idx = blockIdx.x * blockDim.x + threadIdx.x;
    if (idx >= NHEAD * KVLORA * DN) return;
    int h   = idx >> 16;
    int rem = idx & 65535;
    int r   = rem >> 7;
    int d   = rem & 127;
    g_kupT[idx] = __float2half_rn(w_kvb[(size_t)((h << 7) + d) * KVLORA + r]);
}

// kvlatT[b][r][k] = kfull[(b*SEQ+k)*576 + r]
__global__ void transpose_kv_kernel()
{
    int idx = blockIdx.x * blockDim.x + threadIdx.x;
    if (idx >= BATCH * KVLORA * SEQ) return;
    int b   = idx >> 20;
    int rem = idx & ((1 << 20) - 1);
    int r   = rem >> 11;
    int k   = rem & (SEQ - 1);
    g_kvlatT[idx] = g_kfull[(size_t)((b << 11) + k) * CDIM + r];
}

// ---------------- host ----------------
extern "C" void kernel_launch(void* const* d_in, const int* in_sizes, int n_in,
                              void* d_out, int out_size)
{
    (void)in_sizes; (void)n_in; (void)out_size;
    const float* hidden   = (const float*)d_in[0];
    const float* w_qa     = (const float*)d_in[1];
    const float* ln_qa_g  = (const float*)d_in[2];
    const float* ln_qa_b  = (const float*)d_in[3];
    const float* w_qb     = (const float*)d_in[4];
    const float* w_qrope  = (const float*)d_in[5];
    const float* w_kva    = (const float*)d_in[6];
    const float* ln_kva_g = (const float*)d_in[7];
    const float* ln_kva_b = (const float*)d_in[8];
    const float* w_kvb    = (const float*)d_in[9];
    const float* w_o      = (const float*)d_in[10];
    const int*   pos      = (const int*)d_in[11];
    float* out = (float*)d_out;

    cudaFuncSetAttribute(gemm_h, cudaFuncAttributeMaxDynamicSharedMemorySize, GSMEM_H);

    float *q_mixed, *kv_mixed, *q_rope, *scores;
    __half *hid16,*wqa16,*wkva16,*wqb16,*wqr16,*wo16,*kupT16,*vup16;
    __half *qlat16,*qnope16,*qfull16,*kfull16,*kvlT16,*probs16,*attn16,*attnv16;
    cudaGetSymbolAddress((void**)&q_mixed, g_q_mixed);
    cudaGetSymbolAddress((void**)&kv_mixed, g_kv_mixed);
    cudaGetSymbolAddress((void**)&q_rope, g_q_rope);
    cudaGetSymbolAddress((void**)&scores, g_scores);
    cudaGetSymbolAddress((void**)&hid16, g_hidden);
    cudaGetSymbolAddress((void**)&wqa16, g_wqa);
    cudaGetSymbolAddress((void**)&wkva16, g_wkva);
    cudaGetSymbolAddress((void**)&wqb16, g_wqb);
    cudaGetSymbolAddress((void**)&wqr16, g_wqr);
    cudaGetSymbolAddress((void**)&wo16, g_wo);
    cudaGetSymbolAddress((void**)&kupT16, g_kupT);
    cudaGetSymbolAddress((void**)&vup16, g_vup);
    cudaGetSymbolAddress((void**)&qlat16, g_qlat);
    cudaGetSymbolAddress((void**)&qnope16, g_qnope);
    cudaGetSymbolAddress((void**)&qfull16, g_qfull);
    cudaGetSymbolAddress((void**)&kfull16, g_kfull);
    cudaGetSymbolAddress((void**)&kvlT16, g_kvlatT);
    cudaGetSymbolAddress((void**)&probs16, g_probs);
    cudaGetSymbolAddress((void**)&attn16, g_attn);
    cudaGetSymbolAddress((void**)&attnv16, g_attnv);

    auto cvt = [&](const float* x, __half* y, long long n) {
        long long n4 = n >> 2;
        cvt_half_kernel<<<(unsigned)((n4 + 255) / 256), 256>>>(
            (const float4*)x, (__half2*)y, n4);
    };
    auto gemmh = [&](const __half* Ap, const __half* Bp,
                     float* Cf, __half* Chf,
                     int M, int N, int K, int lda, int ldb, int ldc,
                     int Z, int Hdim,
                     long long sAb, long long sAh, long long sBb, long long sBh,
                     long long sCb, long long sCh, int mode) {
        dim3 grid((N + 127) / 128, M / 128, Z);
        gemm_h<<<grid, 256, GSMEM_H>>>(Ap, Bp, Cf, Chf,
                                       N, K, lda, ldb, ldc,
                                       sAb, sAh, sBb, sBh, sCb, sCh, Hdim, mode);
    };

    // operand conversions (fp16)
    cvt(hidden, hid16, (long long)T_TOK * DMODEL);
    cvt(w_qa,   wqa16, (long long)QLORA * DMODEL);
    cvt(w_kva,  wkva16, (long long)CDIM * DMODEL);
    cvt(w_qb,   wqb16, (long long)(NHEAD*DN) * QLORA);
    cvt(w_qrope,wqr16, (long long)(NHEAD*DR) * QLORA);
    cvt(w_o,    wo16,  (long long)DMODEL * (NHEAD*DV));
    cvt(w_kvb + (size_t)NHEAD * DN * KVLORA, vup16, (long long)NHEAD * DV * KVLORA);
    transpose_kup_kernel<<<(NHEAD * KVLORA * DN + 255) / 256, 256>>>(w_kvb);
    rope_tab_kernel<<<(SEQ * 32 + 255) / 256, 256>>>(pos);

    // 1. q_mixed = hidden @ w_qa^T ; LN -> qlat fp16
    gemmh(hid16, wqa16, q_mixed, nullptr,
          T_TOK, QLORA, DMODEL, DMODEL, DMODEL, QLORA, 1, 1, 0,0,0,0,0,0, 0);
    ln_half_kernel<<<T_TOK, 256>>>(q_mixed, qlat16, ln_qa_g, ln_qa_b, QLORA, QLORA, QLORA);

    // 2. kv_mixed = hidden @ w_kva^T ; LN -> kfull[:, :512] ; rope_k -> [:,512:]
    gemmh(hid16, wkva16, kv_mixed, nullptr,
          T_TOK, CDIM, DMODEL, DMODEL, DMODEL, CDIM, 1, 1, 0,0,0,0,0,0, 0);
    ln_half_kernel<<<T_TOK, 256>>>(kv_mixed, kfull16, ln_kva_g, ln_kva_b, KVLORA, CDIM, CDIM);
    rope_k_kernel<<<(T_TOK * 32 + 255) / 256, 256>>>();

    // 3. q_nope fp16 ; q_rope f32 -> rope_q -> qfull
    gemmh(qlat16, wqb16, nullptr, qnope16,
          T_TOK, NHEAD*DN, QLORA, QLORA, QLORA, NHEAD*DN, 1, 1, 0,0,0,0,0,0, 1);
    gemmh(qlat16, wqr16, q_rope, nullptr,
          T_TOK, NHEAD*DR, QLORA, QLORA, QLORA, NHEAD*DR, 1, 1, 0,0,0,0,0,0, 0);
    rope_q_kernel<<<(T_TOK * NHEAD * 32 + 255) / 256, 256>>>();

    // 4. absorb: qfull[:, h, :512] = q_nope_h @ kupT[h]^T  (fp16 out, strided)
    gemmh(qnope16, kupT16, nullptr, qfull16,
          T_TOK, KVLORA, DN, NHEAD*DN, DN, QF_LD, NHEAD, NHEAD,
          0, DN, 0, (long long)KVLORA * DN, 0, CDIM, 1);

    // 5. kvlatT
    transpose_kv_kernel<<<(BATCH * KVLORA * SEQ + 255) / 256, 256>>>();

    // 6. scores = qfull @ kfull^T  (f32 out)
    gemmh(qfull16, kfull16, scores, nullptr,
          SEQ, SEQ, CDIM, QF_LD, CDIM, SEQ, BATCH * NHEAD, NHEAD,
          (long long)SEQ * QF_LD, CDIM,
          (long long)SEQ * CDIM, 0,
          (long long)NHEAD * SEQ * SEQ, (long long)SEQ * SEQ, 0);

    // 7. softmax -> probs fp16
    float scale = (float)(1.0 / sqrt((double)(DN + DR)));
    softmax_half_kernel<<<BATCH * NHEAD * SEQ, 256>>>(scores, probs16, scale);

    // 8. attn = probs @ kvlatT^T  (fp16 out)
    gemmh(probs16, kvlT16, nullptr, attn16,
          SEQ, KVLORA, SEQ, SEQ, SEQ, KVLORA, BATCH * NHEAD, NHEAD,
          (long long)NHEAD * SEQ * SEQ, (long long)SEQ * SEQ,
          (long long)KVLORA * SEQ, 0,
          (long long)NHEAD * SEQ * KVLORA, (long long)SEQ * KVLORA, 1);

    // 9. attn_v = attn @ v_up^T  (fp16 out, strided into [b,s,h*DV])
    gemmh(attn16, vup16, nullptr, attnv16,
          SEQ, DV, KVLORA, KVLORA, KVLORA, NHEAD*DV, BATCH * NHEAD, NHEAD,
          (long long)NHEAD * SEQ * KVLORA, (long long)SEQ * KVLORA,
          0, (long long)DV * KVLORA,
          (long long)SEQ * (NHEAD*DV), DV, 1);

    // 10. out = attn_v @ w_o^T  (f32 out)
    gemmh(attnv16, wo16, out, nullptr,
          T_TOK, DMODEL, NHEAD*DV, NHEAD*DV, NHEAD*DV, DMODEL, 1, 1,
          0,0,0,0,0,0, 0);
}